// round 15
// baseline (speedup 1.0000x reference)
#include <cuda_runtime.h>
#include <cstddef>
#include <cstdint>

#define T_STEPS 2048
#define BATCH   64
#define D_IN    256
#define D_H     256
#define NQ      8
#define ZLD     1032         // 4*256 + 8
#define QSTR    0.5f
#define GRP_CTAS 32          // CTAs per barrier group (one b-tile)

// ---------------- scratch (static device globals; no allocation) ------------
__device__ float g_Z[(size_t)T_STEPS * BATCH * ZLD];   // x-projection + bias
__device__ unsigned long long g_ctr[4 * 16];           // per-group monotonic ctr

// ---------------------------------------------------------------------------
// packed fp32x2 helpers
// ---------------------------------------------------------------------------
__device__ __forceinline__ unsigned long long pack2(float a, float b) {
    unsigned long long r;
    asm("mov.b64 %0, {%1, %2};" : "=l"(r) : "f"(a), "f"(b));
    return r;
}
__device__ __forceinline__ void unpack2(unsigned long long v, float& a, float& b) {
    asm("mov.b64 {%0, %1}, %2;" : "=f"(a), "=f"(b) : "l"(v));
}
__device__ __forceinline__ void fma2(unsigned long long& d,
                                     unsigned long long a, unsigned long long b) {
    asm("fma.rn.f32x2 %0, %1, %2, %0;" : "+l"(d) : "l"(a), "l"(b));
}

// ---------------------------------------------------------------------------
// Kernel 1: Z = X @ Wx + bias. 128m x 128n tiles, 256 threads, packed FFMA2
// (verified rounds 11/12/14 — unchanged).
// ---------------------------------------------------------------------------
__global__ void __launch_bounds__(256)
xproj_kernel(const float* __restrict__ X,
             const float* __restrict__ Wf, const float* __restrict__ bf,
             const float* __restrict__ Wi, const float* __restrict__ bi,
             const float* __restrict__ Wg, const float* __restrict__ bg,
             const float* __restrict__ Wo, const float* __restrict__ bo,
             const float* __restrict__ Wq, const float* __restrict__ bq)
{
    __shared__ float Xs[8][132];   // [k][m]
    __shared__ float Bs[8][132];   // [k][n]

    const int row0 = blockIdx.x * 128;
    const int nt   = blockIdx.y;          // 0..8

    const float* W; const float* bias; int ld, wc0, col0, nvalid;
    if (nt < 8) {
        int gate = nt >> 1;
        W    = (gate == 0) ? Wf : (gate == 1) ? Wi : (gate == 2) ? Wg : Wo;
        bias = (gate == 0) ? bf : (gate == 1) ? bi : (gate == 2) ? bg : bo;
        ld = 256; wc0 = (nt & 1) * 128; col0 = nt * 128; nvalid = 128;
    } else {
        W = Wq; bias = bq; ld = 8; wc0 = 0; col0 = 1024; nvalid = 8;
    }

    const int tid = threadIdx.x;          // 256
    const int tx  = tid & 15;
    const int ty  = tid >> 4;

    unsigned long long acc2[8][4];
    #pragma unroll
    for (int i = 0; i < 8; i++)
        #pragma unroll
        for (int j = 0; j < 4; j++) acc2[i][j] = 0ull;

    for (int k0 = 0; k0 < 256; k0 += 8) {
        {
            int m = tid >> 1, kq = tid & 1;
            float4 v = *(const float4*)(X + (size_t)(row0 + m) * 256 + k0 + kq * 4);
            Xs[kq * 4 + 0][m] = v.x;
            Xs[kq * 4 + 1][m] = v.y;
            Xs[kq * 4 + 2][m] = v.z;
            Xs[kq * 4 + 3][m] = v.w;
        }
        {
            int k = tid >> 5, n4 = tid & 31;
            float4 w4 = { 0.f, 0.f, 0.f, 0.f };
            if (n4 * 4 < nvalid)
                w4 = *(const float4*)(W + (size_t)(k0 + k) * ld + wc0 + n4 * 4);
            *(float4*)&Bs[k][n4 * 4] = w4;
        }
        __syncthreads();

        #pragma unroll
        for (int kk = 0; kk < 8; kk++) {
            float4 a0 = *(const float4*)&Xs[kk][ty * 4];
            float4 a1 = *(const float4*)&Xs[kk][64 + ty * 4];
            float4 b0 = *(const float4*)&Bs[kk][tx * 4];
            float4 b1 = *(const float4*)&Bs[kk][64 + tx * 4];
            unsigned long long bp[4] = {
                pack2(b0.x, b0.y), pack2(b0.z, b0.w),
                pack2(b1.x, b1.y), pack2(b1.z, b1.w)
            };
            float a[8] = { a0.x, a0.y, a0.z, a0.w, a1.x, a1.y, a1.z, a1.w };
            #pragma unroll
            for (int i = 0; i < 8; i++) {
                unsigned long long ap = pack2(a[i], a[i]);
                fma2(acc2[i][0], ap, bp[0]);
                fma2(acc2[i][1], ap, bp[1]);
                fma2(acc2[i][2], ap, bp[2]);
                fma2(acc2[i][3], ap, bp[3]);
            }
        }
        __syncthreads();
    }

    #pragma unroll
    for (int i = 0; i < 8; i++) {
        int r = row0 + ((i < 4) ? (ty * 4 + i) : (64 + ty * 4 + i - 4));
        #pragma unroll
        for (int j = 0; j < 4; j++) {
            int nb = (j < 2) ? (tx * 4 + j * 2) : (64 + tx * 4 + (j - 2) * 2);
            float lo, hi;
            unpack2(acc2[i][j], lo, hi);
            if (nb < nvalid)
                g_Z[(size_t)r * ZLD + col0 + nb] = lo + bias[wc0 + nb];
            if (nb + 1 < nvalid)
                g_Z[(size_t)r * ZLD + col0 + nb + 1] = hi + bias[wc0 + nb + 1];
        }
    }
}

__device__ __forceinline__ float sigmoidf_(float x) {
    return 1.f / (1.f + __expf(-x));
}
// MUFU-based tanh: 2/(1+e^{-2x}) - 1; saturates correctly, err ~1e-7
__device__ __forceinline__ float tanhf_(float x) {
    return 2.f / (1.f + __expf(-2.f * x)) - 1.f;
}

__device__ __forceinline__ void red_add_u64(unsigned long long* p) {
    asm volatile("red.global.gpu.add.u64 [%0], %1;" :: "l"(p), "l"(1ull) : "memory");
}
__device__ __forceinline__ unsigned long long ld_vol_u64(const unsigned long long* p) {
    unsigned long long v;
    asm volatile("ld.volatile.global.u64 %0, [%1];" : "=l"(v) : "l"(p));
    return v;
}

// ---------------------------------------------------------------------------
// Kernel 2: persistent recurrence — R6/R14 verified core with three critical-
// path cuts: (1) single tid0 threadfence instead of 128 owner fences,
// (2) hard spin (no nanosleep) in the barrier poll, (3) MUFU-based tanh.
// 128 CTAs (4 b-tiles x 32 u-tiles), 512 threads.
// ---------------------------------------------------------------------------
__global__ void __launch_bounds__(512, 1)
lstm_persistent(const float* __restrict__ Wf,
                const float* __restrict__ Wi,
                const float* __restrict__ Wg,
                const float* __restrict__ Wo,
                const float* __restrict__ Wq,
                float* __restrict__ stacked,   // [T,B,256]
                float* __restrict__ hx_out,    // [B,256]
                float* __restrict__ cx_out)    // [B,256]
{
    __shared__ float sm_h[16 * 264];        // hx tile, padded rows
    __shared__ float sm_red[16 * 352];      // [warp][uu(44)][c2*20+j*5+g]

    const int tid  = threadIdx.x;           // 512
    const int warp = tid >> 5;              // 0..15
    const int lane = tid & 31;
    const int b0   = blockIdx.x * 16;       // gridDim.x = 4
    const int u0   = blockIdx.y * 8;        // gridDim.y = 32

    const int uu   = lane & 7;
    const int kcl  = lane >> 3;             // 0..3
    const int kch  = warp & 7;              // 0..7
    const int rh   = warp >> 3;             // 0..1
    const int k0   = (kch * 4 + kcl) * 8;   // 8-k chunk base

    // ---- weights: packed k-pairs, 5 gates x 4 pairs, in registers ----
    unsigned long long wv[5][4];
    {
        const float* Wp[4] = { Wf, Wi, Wg, Wo };
        #pragma unroll
        for (int g = 0; g < 4; g++)
            #pragma unroll
            for (int kp = 0; kp < 4; kp++) {
                int k = 256 + k0 + 2 * kp;
                wv[g][kp] = pack2(Wp[g][(size_t)k * 256 + u0 + uu],
                                  Wp[g][(size_t)(k + 1) * 256 + u0 + uu]);
            }
        #pragma unroll
        for (int kp = 0; kp < 4; kp++) {
            int k = 256 + k0 + 2 * kp;
            wv[4][kp] = pack2(Wq[(size_t)k * 8 + uu], Wq[(size_t)(k + 1) * 8 + uu]);
        }
    }

    // ---- owner mapping: tid < 128 -> one (row, unit) output ----
    const int o_row = tid >> 3;
    const int o_uu  = tid & 7;
    const int ob    = b0 + o_row;
    const int oug   = u0 + o_uu;
    const float* o_z = g_Z + (size_t)ob * ZLD;
    float c = 0.f, h = 0.f;

    unsigned long long* ctr = &g_ctr[blockIdx.x * 16];
    unsigned long long base = 0ull;         // thread0 only

    for (int t = 0; t < T_STEPS; t++) {
        // prefetch Z (independent of recurrence) before the wait
        float zF = 0.f, zI = 0.f, zG = 0.f, zO = 0.f, zQ = 0.f;
        if (tid < 128) {
            const float* z = o_z + (size_t)t * BATCH * ZLD;
            zF = __ldg(z + oug);
            zI = __ldg(z + 256 + oug);
            zG = __ldg(z + 512 + oug);
            zO = __ldg(z + 768 + oug);
            zQ = __ldg(z + 1024 + o_uu);
        }

        // ---- wait for step t-1 of this b-tile group (hard spin) ----
        if (t > 0) {
            if (tid == 0) {
                unsigned long long target = base + (unsigned long long)t * GRP_CTAS;
                while (ld_vol_u64(ctr) < target) { }
            }
            __syncthreads();
        }

        // ---- stage hx tile (stacked[t-1], zeros at t==0) ----
        const float4* hsrc = (const float4*)(stacked + ((size_t)(t - 1) * BATCH + b0) * 256);
        #pragma unroll
        for (int i = 0; i < 2; i++) {
            int idx = tid + i * 512;            // 0..1023
            int row = idx >> 6, k4 = idx & 63;
            float4 v;
            if (t == 0) { v.x = v.y = v.z = v.w = 0.f; }
            else        { v = __ldcg(hsrc + (size_t)row * 64 + k4); }
            *(float4*)(sm_h + row * 264 + k4 * 4) = v;
        }
        __syncthreads();

        // ---- two 4-row passes: dots + reduce (verified core) ----
        #pragma unroll
        for (int c2 = 0; c2 < 2; c2++) {
            unsigned long long acc[4][5];
            #pragma unroll
            for (int j = 0; j < 4; j++)
                #pragma unroll
                for (int g = 0; g < 5; g++) acc[j][g] = 0ull;

            #pragma unroll
            for (int j = 0; j < 4; j++) {
                const float* hrow = sm_h + (rh * 8 + c2 * 4 + j) * 264 + k0;
                float4 hv0 = *(const float4*)(hrow);
                float4 hv1 = *(const float4*)(hrow + 4);
                unsigned long long hk0 = pack2(hv0.x, hv0.y);
                unsigned long long hk1 = pack2(hv0.z, hv0.w);
                unsigned long long hk2 = pack2(hv1.x, hv1.y);
                unsigned long long hk3 = pack2(hv1.z, hv1.w);
                #pragma unroll
                for (int g = 0; g < 5; g++) {
                    fma2(acc[j][g], hk0, wv[g][0]);
                    fma2(acc[j][g], hk1, wv[g][1]);
                    fma2(acc[j][g], hk2, wv[g][2]);
                    fma2(acc[j][g], hk3, wv[g][3]);
                }
            }

            // horizontal + reduce over kcl (lane bits 3,4)
            float v[20];
            #pragma unroll
            for (int j = 0; j < 4; j++)
                #pragma unroll
                for (int g = 0; g < 5; g++) {
                    float lo, hi;
                    unpack2(acc[j][g], lo, hi);
                    v[j * 5 + g] = lo + hi;
                }
            #pragma unroll
            for (int m = 0; m < 20; m++) {
                v[m] += __shfl_xor_sync(0xffffffffu, v[m], 8);
                v[m] += __shfl_xor_sync(0xffffffffu, v[m], 16);
            }
            if (kcl == 0) {
                float* dst = sm_red + warp * 352 + uu * 44 + c2 * 20;
                #pragma unroll
                for (int q4 = 0; q4 < 5; q4++)
                    *(float4*)(dst + q4 * 4) = make_float4(v[q4*4], v[q4*4+1],
                                                           v[q4*4+2], v[q4*4+3]);
            }
        }
        __syncthreads();

        // ---- owners finalize (no per-owner fence) ----
        if (tid < 128) {
            const int rh_o = o_row >> 3;
            const int rr   = o_row & 7;
            const int c2_o = rr >> 2;
            const int j_o  = rr & 3;
            float aF = zF, aI = zI, aG = zG, aO = zO, aQ = zQ;
            #pragma unroll
            for (int w2 = 0; w2 < 8; w2++) {
                const float* src = sm_red + (rh_o * 8 + w2) * 352 + o_uu * 44
                                 + c2_o * 20 + j_o * 5;
                aF += src[0]; aI += src[1]; aG += src[2]; aO += src[3]; aQ += src[4];
            }

            float s = tanhf_(aQ);
            s += __shfl_xor_sync(0xffffffffu, s, 1);
            s += __shfl_xor_sync(0xffffffffu, s, 2);
            s += __shfl_xor_sync(0xffffffffu, s, 4);
            const float qout = sigmoidf_(s);

            const float f = (1.f - QSTR) * sigmoidf_(aF) + QSTR * qout;
            const float i = sigmoidf_(aI);
            const float g = tanhf_(aG);
            const float o = sigmoidf_(aO);

            c = f * c + i * g;
            h = o * tanhf_(c);

            __stcg(stacked + ((size_t)t * BATCH + ob) * 256 + oug, h);
        }
        __syncthreads();   // all owner stores done (CTA-ordered)

        // ---- arrive: ONE fence covers all owner stores (barrier-ordered) ----
        if (tid == 0) {
            __threadfence();
            if (t == 0) {
                unsigned long long a = atomicAdd(ctr, 1ull);
                base = (a / GRP_CTAS) * GRP_CTAS;   // counter base this launch
            } else {
                red_add_u64(ctr);
            }
        }
    }

    if (tid < 128) {
        hx_out[ob * 256 + oug] = h;
        cx_out[ob * 256 + oug] = c;
    }
}

// ---------------------------------------------------------------------------
extern "C" void kernel_launch(void* const* d_in, const int* in_sizes, int n_in,
                              void* d_out, int out_size)
{
    const float* X  = (const float*)d_in[0];
    const float* Wf = (const float*)d_in[1];
    const float* bf = (const float*)d_in[2];
    const float* Wi = (const float*)d_in[3];
    const float* bi = (const float*)d_in[4];
    const float* Wg = (const float*)d_in[5];
    const float* bg = (const float*)d_in[6];
    const float* Wo = (const float*)d_in[7];
    const float* bo = (const float*)d_in[8];
    const float* Wq = (const float*)d_in[9];
    const float* bq = (const float*)d_in[10];

    float* out     = (float*)d_out;
    float* stacked = out;                                  // [T,B,256]
    float* hx_out  = out + (size_t)T_STEPS * BATCH * D_H;  // [B,256]
    float* cx_out  = hx_out + BATCH * D_H;                 // [B,256]

    // 1) precompute input projections (packed FFMA2 GEMM)
    dim3 g1(T_STEPS * BATCH / 128, 9);
    xproj_kernel<<<g1, 256>>>(X, Wf, bf, Wi, bi, Wg, bg, Wo, bo, Wq, bq);

    // 2) persistent recurrence
    dim3 g2(4, 32);
    lstm_persistent<<<g2, 512>>>(Wf, Wi, Wg, Wo, Wq, stacked, hx_out, cx_out);
}

// round 16
// speedup vs baseline: 1.0083x; 1.0083x over previous
#include <cuda_runtime.h>
#include <cstddef>
#include <cstdint>

#define T_STEPS 2048
#define BATCH   64
#define D_IN    256
#define D_H     256
#define NQ      8
#define ZLD     1032         // 4*256 + 8
#define QSTR    0.5f
#define GRP_CTAS 32          // CTAs per barrier group (one b-tile)

// ---------------- scratch (static device globals; no allocation) ------------
__device__ float g_Z[(size_t)T_STEPS * BATCH * ZLD];   // x-projection + bias
__device__ unsigned long long g_ctr[4 * 16];           // per-group monotonic ctr

// ---------------------------------------------------------------------------
// packed fp32x2 helpers
// ---------------------------------------------------------------------------
__device__ __forceinline__ unsigned long long pack2(float a, float b) {
    unsigned long long r;
    asm("mov.b64 %0, {%1, %2};" : "=l"(r) : "f"(a), "f"(b));
    return r;
}
__device__ __forceinline__ void unpack2(unsigned long long v, float& a, float& b) {
    asm("mov.b64 {%0, %1}, %2;" : "=f"(a), "=f"(b) : "l"(v));
}
__device__ __forceinline__ void fma2(unsigned long long& d,
                                     unsigned long long a, unsigned long long b) {
    asm("fma.rn.f32x2 %0, %1, %2, %0;" : "+l"(d) : "l"(a), "l"(b));
}

// ---------------------------------------------------------------------------
// Kernel 1: Z = X @ Wx + bias. 128m x 128n tiles, 256 threads, packed FFMA2,
// DOUBLE-BUFFERED smem pipeline (LDG of next k-chunk hidden under FMA).
// ---------------------------------------------------------------------------
__global__ void __launch_bounds__(256)
xproj_kernel(const float* __restrict__ X,
             const float* __restrict__ Wf, const float* __restrict__ bf,
             const float* __restrict__ Wi, const float* __restrict__ bi,
             const float* __restrict__ Wg, const float* __restrict__ bg,
             const float* __restrict__ Wo, const float* __restrict__ bo,
             const float* __restrict__ Wq, const float* __restrict__ bq)
{
    __shared__ float Xs[2][8][132];   // [buf][k][m]
    __shared__ float Bs[2][8][132];   // [buf][k][n]

    const int row0 = blockIdx.x * 128;
    const int nt   = blockIdx.y;          // 0..8

    const float* W; const float* bias; int ld, wc0, col0, nvalid;
    if (nt < 8) {
        int gate = nt >> 1;
        W    = (gate == 0) ? Wf : (gate == 1) ? Wi : (gate == 2) ? Wg : Wo;
        bias = (gate == 0) ? bf : (gate == 1) ? bi : (gate == 2) ? bg : bo;
        ld = 256; wc0 = (nt & 1) * 128; col0 = nt * 128; nvalid = 128;
    } else {
        W = Wq; bias = bq; ld = 8; wc0 = 0; col0 = 1024; nvalid = 8;
    }

    const int tid = threadIdx.x;          // 256
    const int tx  = tid & 15;
    const int ty  = tid >> 4;

    // staging thread roles
    const int xm = tid >> 1, xkq = tid & 1;       // X: row, k-quad
    const int bk = tid >> 5, bn4 = tid & 31;      // B: k, n-quad
    const bool bvalid = (bn4 * 4 < nvalid);

    unsigned long long acc2[8][4];
    #pragma unroll
    for (int i = 0; i < 8; i++)
        #pragma unroll
        for (int j = 0; j < 4; j++) acc2[i][j] = 0ull;

    // ---- prologue: load chunk 0 into buffer 0 ----
    {
        float4 xv = __ldg((const float4*)(X + (size_t)(row0 + xm) * 256 + xkq * 4));
        Xs[0][xkq * 4 + 0][xm] = xv.x;
        Xs[0][xkq * 4 + 1][xm] = xv.y;
        Xs[0][xkq * 4 + 2][xm] = xv.z;
        Xs[0][xkq * 4 + 3][xm] = xv.w;
        float4 wv4 = { 0.f, 0.f, 0.f, 0.f };
        if (bvalid)
            wv4 = __ldg((const float4*)(W + (size_t)bk * ld + wc0 + bn4 * 4));
        *(float4*)&Bs[0][bk][bn4 * 4] = wv4;
    }
    __syncthreads();

    #pragma unroll 1
    for (int it = 0; it < 32; it++) {
        const int cur = it & 1;

        // issue next chunk's LDGs (latency hidden under the FMA block below)
        float4 xv, wv4;
        if (it < 31) {
            const int kn = (it + 1) * 8;
            xv = __ldg((const float4*)(X + (size_t)(row0 + xm) * 256 + kn + xkq * 4));
            wv4 = make_float4(0.f, 0.f, 0.f, 0.f);
            if (bvalid)
                wv4 = __ldg((const float4*)(W + (size_t)(kn + bk) * ld + wc0 + bn4 * 4));
        }

        // FMA on current buffer
        #pragma unroll
        for (int kk = 0; kk < 8; kk++) {
            float4 a0 = *(const float4*)&Xs[cur][kk][ty * 4];
            float4 a1 = *(const float4*)&Xs[cur][kk][64 + ty * 4];
            float4 b0 = *(const float4*)&Bs[cur][kk][tx * 4];
            float4 b1 = *(const float4*)&Bs[cur][kk][64 + tx * 4];
            unsigned long long bp[4] = {
                pack2(b0.x, b0.y), pack2(b0.z, b0.w),
                pack2(b1.x, b1.y), pack2(b1.z, b1.w)
            };
            float a[8] = { a0.x, a0.y, a0.z, a0.w, a1.x, a1.y, a1.z, a1.w };
            #pragma unroll
            for (int i = 0; i < 8; i++) {
                unsigned long long ap = pack2(a[i], a[i]);
                fma2(acc2[i][0], ap, bp[0]);
                fma2(acc2[i][1], ap, bp[1]);
                fma2(acc2[i][2], ap, bp[2]);
                fma2(acc2[i][3], ap, bp[3]);
            }
        }

        // store next chunk into the alternate buffer (no one reads it yet)
        if (it < 31) {
            const int nb = cur ^ 1;
            Xs[nb][xkq * 4 + 0][xm] = xv.x;
            Xs[nb][xkq * 4 + 1][xm] = xv.y;
            Xs[nb][xkq * 4 + 2][xm] = xv.z;
            Xs[nb][xkq * 4 + 3][xm] = xv.w;
            *(float4*)&Bs[nb][bk][bn4 * 4] = wv4;
        }
        __syncthreads();
    }

    #pragma unroll
    for (int i = 0; i < 8; i++) {
        int r = row0 + ((i < 4) ? (ty * 4 + i) : (64 + ty * 4 + i - 4));
        #pragma unroll
        for (int j = 0; j < 4; j++) {
            int nb = (j < 2) ? (tx * 4 + j * 2) : (64 + tx * 4 + (j - 2) * 2);
            float lo, hi;
            unpack2(acc2[i][j], lo, hi);
            if (nb < nvalid)
                g_Z[(size_t)r * ZLD + col0 + nb] = lo + bias[wc0 + nb];
            if (nb + 1 < nvalid)
                g_Z[(size_t)r * ZLD + col0 + nb + 1] = hi + bias[wc0 + nb + 1];
        }
    }
}

__device__ __forceinline__ float sigmoidf_(float x) {
    return 1.f / (1.f + __expf(-x));
}

__device__ __forceinline__ void red_add_u64(unsigned long long* p) {
    asm volatile("red.global.gpu.add.u64 [%0], %1;" :: "l"(p), "l"(1ull) : "memory");
}
__device__ __forceinline__ unsigned long long ld_vol_u64(const unsigned long long* p) {
    unsigned long long v;
    asm volatile("ld.volatile.global.u64 %0, [%1];" : "=l"(v) : "l"(p));
    return v;
}

// ---------------------------------------------------------------------------
// Kernel 2: persistent recurrence — VERBATIM R6/R14 verified kernel (7.83 ms).
// 128 CTAs (4 b-tiles x 32 u-tiles), 512 threads.
// ---------------------------------------------------------------------------
__global__ void __launch_bounds__(512, 1)
lstm_persistent(const float* __restrict__ Wf,
                const float* __restrict__ Wi,
                const float* __restrict__ Wg,
                const float* __restrict__ Wo,
                const float* __restrict__ Wq,
                float* __restrict__ stacked,   // [T,B,256]
                float* __restrict__ hx_out,    // [B,256]
                float* __restrict__ cx_out)    // [B,256]
{
    __shared__ float sm_h[16 * 264];        // hx tile, padded rows
    __shared__ float sm_red[16 * 352];      // [warp][uu(44)][c2*20+j*5+g]

    const int tid  = threadIdx.x;           // 512
    const int warp = tid >> 5;              // 0..15
    const int lane = tid & 31;
    const int b0   = blockIdx.x * 16;       // gridDim.x = 4
    const int u0   = blockIdx.y * 8;        // gridDim.y = 32

    const int uu   = lane & 7;
    const int kcl  = lane >> 3;             // 0..3
    const int kch  = warp & 7;              // 0..7
    const int rh   = warp >> 3;             // 0..1
    const int k0   = (kch * 4 + kcl) * 8;   // 8-k chunk base

    // ---- weights: packed k-pairs, 5 gates x 4 pairs, in registers ----
    unsigned long long wv[5][4];
    {
        const float* Wp[4] = { Wf, Wi, Wg, Wo };
        #pragma unroll
        for (int g = 0; g < 4; g++)
            #pragma unroll
            for (int kp = 0; kp < 4; kp++) {
                int k = 256 + k0 + 2 * kp;
                wv[g][kp] = pack2(Wp[g][(size_t)k * 256 + u0 + uu],
                                  Wp[g][(size_t)(k + 1) * 256 + u0 + uu]);
            }
        #pragma unroll
        for (int kp = 0; kp < 4; kp++) {
            int k = 256 + k0 + 2 * kp;
            wv[4][kp] = pack2(Wq[(size_t)k * 8 + uu], Wq[(size_t)(k + 1) * 8 + uu]);
        }
    }

    // ---- owner mapping: tid < 128 -> one (row, unit) output ----
    const int o_row = tid >> 3;
    const int o_uu  = tid & 7;
    const int ob    = b0 + o_row;
    const int oug   = u0 + o_uu;
    const float* o_z = g_Z + (size_t)ob * ZLD;
    float c = 0.f, h = 0.f;

    unsigned long long* ctr = &g_ctr[blockIdx.x * 16];
    unsigned long long base = 0ull;         // thread0 only

    for (int t = 0; t < T_STEPS; t++) {
        // prefetch Z (independent of recurrence) before the wait
        float zF = 0.f, zI = 0.f, zG = 0.f, zO = 0.f, zQ = 0.f;
        if (tid < 128) {
            const float* z = o_z + (size_t)t * BATCH * ZLD;
            zF = __ldg(z + oug);
            zI = __ldg(z + 256 + oug);
            zG = __ldg(z + 512 + oug);
            zO = __ldg(z + 768 + oug);
            zQ = __ldg(z + 1024 + o_uu);
        }

        // ---- wait for step t-1 of this b-tile group ----
        if (t > 0) {
            if (tid == 0) {
                unsigned long long target = base + (unsigned long long)t * GRP_CTAS;
                while (ld_vol_u64(ctr) < target)
                    __nanosleep(16);
            }
            __syncthreads();
        }

        // ---- stage hx tile (stacked[t-1], zeros at t==0) ----
        const float4* hsrc = (const float4*)(stacked + ((size_t)(t - 1) * BATCH + b0) * 256);
        #pragma unroll
        for (int i = 0; i < 2; i++) {
            int idx = tid + i * 512;            // 0..1023
            int row = idx >> 6, k4 = idx & 63;
            float4 v;
            if (t == 0) { v.x = v.y = v.z = v.w = 0.f; }
            else        { v = __ldcg(hsrc + (size_t)row * 64 + k4); }
            *(float4*)(sm_h + row * 264 + k4 * 4) = v;
        }
        __syncthreads();

        // ---- two 4-row passes: dots + reduce ----
        #pragma unroll
        for (int c2 = 0; c2 < 2; c2++) {
            unsigned long long acc[4][5];
            #pragma unroll
            for (int j = 0; j < 4; j++)
                #pragma unroll
                for (int g = 0; g < 5; g++) acc[j][g] = 0ull;

            #pragma unroll
            for (int j = 0; j < 4; j++) {
                const float* hrow = sm_h + (rh * 8 + c2 * 4 + j) * 264 + k0;
                float4 hv0 = *(const float4*)(hrow);
                float4 hv1 = *(const float4*)(hrow + 4);
                unsigned long long hk0 = pack2(hv0.x, hv0.y);
                unsigned long long hk1 = pack2(hv0.z, hv0.w);
                unsigned long long hk2 = pack2(hv1.x, hv1.y);
                unsigned long long hk3 = pack2(hv1.z, hv1.w);
                #pragma unroll
                for (int g = 0; g < 5; g++) {
                    fma2(acc[j][g], hk0, wv[g][0]);
                    fma2(acc[j][g], hk1, wv[g][1]);
                    fma2(acc[j][g], hk2, wv[g][2]);
                    fma2(acc[j][g], hk3, wv[g][3]);
                }
            }

            // horizontal + reduce over kcl (lane bits 3,4)
            float v[20];
            #pragma unroll
            for (int j = 0; j < 4; j++)
                #pragma unroll
                for (int g = 0; g < 5; g++) {
                    float lo, hi;
                    unpack2(acc[j][g], lo, hi);
                    v[j * 5 + g] = lo + hi;
                }
            #pragma unroll
            for (int m = 0; m < 20; m++) {
                v[m] += __shfl_xor_sync(0xffffffffu, v[m], 8);
                v[m] += __shfl_xor_sync(0xffffffffu, v[m], 16);
            }
            if (kcl == 0) {
                float* dst = sm_red + warp * 352 + uu * 44 + c2 * 20;
                #pragma unroll
                for (int q4 = 0; q4 < 5; q4++)
                    *(float4*)(dst + q4 * 4) = make_float4(v[q4*4], v[q4*4+1],
                                                           v[q4*4+2], v[q4*4+3]);
            }
        }
        __syncthreads();

        // ---- owners finalize ----
        if (tid < 128) {
            const int rh_o = o_row >> 3;
            const int rr   = o_row & 7;
            const int c2_o = rr >> 2;
            const int j_o  = rr & 3;
            float aF = zF, aI = zI, aG = zG, aO = zO, aQ = zQ;
            #pragma unroll
            for (int w2 = 0; w2 < 8; w2++) {
                const float* src = sm_red + (rh_o * 8 + w2) * 352 + o_uu * 44
                                 + c2_o * 20 + j_o * 5;
                aF += src[0]; aI += src[1]; aG += src[2]; aO += src[3]; aQ += src[4];
            }

            float s = tanhf(aQ);
            s += __shfl_xor_sync(0xffffffffu, s, 1);
            s += __shfl_xor_sync(0xffffffffu, s, 2);
            s += __shfl_xor_sync(0xffffffffu, s, 4);
            const float qout = sigmoidf_(s);

            const float f = (1.f - QSTR) * sigmoidf_(aF) + QSTR * qout;
            const float i = sigmoidf_(aI);
            const float g = tanhf(aG);
            const float o = sigmoidf_(aO);

            c = f * c + i * g;
            h = o * tanhf(c);

            __stcg(stacked + ((size_t)t * BATCH + ob) * 256 + oug, h);
            __threadfence();   // h visible before the arrive below
        }
        __syncthreads();

        // ---- arrive ----
        if (tid == 0) {
            if (t == 0) {
                unsigned long long a = atomicAdd(ctr, 1ull);
                base = (a / GRP_CTAS) * GRP_CTAS;   // counter base this launch
            } else {
                red_add_u64(ctr);
            }
        }
    }

    if (tid < 128) {
        hx_out[ob * 256 + oug] = h;
        cx_out[ob * 256 + oug] = c;
    }
}

// ---------------------------------------------------------------------------
extern "C" void kernel_launch(void* const* d_in, const int* in_sizes, int n_in,
                              void* d_out, int out_size)
{
    const float* X  = (const float*)d_in[0];
    const float* Wf = (const float*)d_in[1];
    const float* bf = (const float*)d_in[2];
    const float* Wi = (const float*)d_in[3];
    const float* bi = (const float*)d_in[4];
    const float* Wg = (const float*)d_in[5];
    const float* bg = (const float*)d_in[6];
    const float* Wo = (const float*)d_in[7];
    const float* bo = (const float*)d_in[8];
    const float* Wq = (const float*)d_in[9];
    const float* bq = (const float*)d_in[10];

    float* out     = (float*)d_out;
    float* stacked = out;                                  // [T,B,256]
    float* hx_out  = out + (size_t)T_STEPS * BATCH * D_H;  // [B,256]
    float* cx_out  = hx_out + BATCH * D_H;                 // [B,256]

    // 1) precompute input projections (pipelined packed-FFMA2 GEMM)
    dim3 g1(T_STEPS * BATCH / 128, 9);
    xproj_kernel<<<g1, 256>>>(X, Wf, bf, Wi, bi, Wg, bg, Wo, bo, Wq, bq);

    // 2) persistent recurrence (verified R6/R14 kernel)
    dim3 g2(4, 32);
    lstm_persistent<<<g2, 512>>>(Wf, Wi, Wg, Wo, Wq, stacked, hx_out, cx_out);
}